// round 17
// baseline (speedup 1.0000x reference)
#include <cuda_runtime.h>
#include <cuda_fp16.h>
#include <cstdint>
#include <math.h>

#define ENC 2048
#define DEC 512
#define ATTD 512
#define BATCH 256
#define LSEQ 196
#define MROWS (BATCH * LSEQ)      // 50176
#define TILE_M 128
#define NCTA (MROWS / TILE_M)     // 392
#define KBLK 64
#define NKB (ENC / KBLK)          // 32
#define NB_CHUNKS 4               // 512 / 128
#define NSTG 3
#define XSTG 16384                // x: 128 rows x 64k x 2B
#define WSTG 16384                // W: 128 n-rows x 64k x 2B
#define WBASE (NSTG * XSTG)       // 49152
#define DYN_BYTES (WBASE + NSTG * WSTG + 128)  // 98432 (-> 2 CTAs/SM)
#define NTH 256

// ---------------- scratch globals ----------------
__device__ float g_att2[BATCH * ATTD];
__device__ float g_gate[BATCH];
__device__ float g_att[MROWS];
// W transposed fp16: [n=512][k=2048]
__device__ __align__(16) unsigned char g_Wt[512u * 2048u * 2u];
// x as fp16 (written in nb==0 pass, re-read by nb>=1 and by z): [m][k]
__device__ __align__(16) __half g_Xh[(size_t)MROWS * ENC];

// ---------------- helpers ----------------
__device__ __forceinline__ uint32_t smem_u32(const void* p) {
    uint32_t a;
    asm("{ .reg .u64 t; cvta.to.shared.u64 t, %1; cvt.u32.u64 %0, t; }" : "=r"(a) : "l"(p));
    return a;
}
__device__ __forceinline__ uint32_t packh2(__half a, __half b) {
    __half2 t = __halves2half2(a, b);
    return *reinterpret_cast<uint32_t*>(&t);
}
__device__ __forceinline__ void stg_cs_128(void* p, uint4 v) {
    asm volatile("st.global.cs.v4.b32 [%0], {%1, %2, %3, %4};"
        :: "l"(p), "r"(v.x), "r"(v.y), "r"(v.z), "r"(v.w) : "memory");
}
#define LDSM_X4(r, addr) \
    asm volatile("ldmatrix.sync.aligned.m8n8.x4.shared.b16 {%0,%1,%2,%3}, [%4];" \
        : "=r"((r)[0]), "=r"((r)[1]), "=r"((r)[2]), "=r"((r)[3]) : "r"(addr))
#define MMA_F16F32(c, a, b) \
    asm volatile("mma.sync.aligned.m16n8k16.row.col.f32.f16.f16.f32 " \
        "{%0,%1,%2,%3}, {%4,%5,%6,%7}, {%8,%9}, {%0,%1,%2,%3};" \
        : "+f"((c)[0]), "+f"((c)[1]), "+f"((c)[2]), "+f"((c)[3]) \
        : "r"((a)[0]), "r"((a)[1]), "r"((a)[2]), "r"((a)[3]), "r"((b)[0]), "r"((b)[1]))
#define CP_ASYNC16(dst, src) \
    asm volatile("cp.async.ca.shared.global [%0], [%1], 16;" :: "r"(dst), "l"(src) : "memory")
#define CP_COMMIT() asm volatile("cp.async.commit_group;" ::: "memory")
#define CP_WAIT1()  asm volatile("cp.async.wait_group 1;" ::: "memory")
#define CP_WAIT0()  asm volatile("cp.async.wait_group 0;" ::: "memory")

// ---------------------------------------------------------------------------
// prep_w: W_enc [2048 k][512 n] fp32 -> g_Wt fp16 [n][k]
// ---------------------------------------------------------------------------
__global__ __launch_bounds__(256) void prep_w(const float* __restrict__ W_enc) {
    __shared__ float tile[64][65];
    const int k0 = blockIdx.x * 64, n0 = blockIdx.y * 64;
    const int tid = threadIdx.x;
    for (int i = tid; i < 64 * 64; i += 256) {
        int kk = i >> 6, nn = i & 63;
        tile[kk][nn] = W_enc[(size_t)(k0 + kk) * ATTD + n0 + nn];
    }
    __syncthreads();
    for (int i = tid; i < 512; i += 256) {
        int nn = i >> 3, ch = i & 7;
        uint32_t w[4];
#pragma unroll
        for (int j = 0; j < 4; j++) {
            w[j] = packh2(__float2half_rn(tile[ch * 8 + 2 * j][nn]),
                          __float2half_rn(tile[ch * 8 + 2 * j + 1][nn]));
        }
        *reinterpret_cast<uint4*>(g_Wt + (size_t)(n0 + nn) * 4096 +
                                  (size_t)(k0 + ch * 8) * 2) =
            make_uint4(w[0], w[1], w[2], w[3]);
    }
}

// ---------------------------------------------------------------------------
// att2 + gate (fp32)
// ---------------------------------------------------------------------------
__global__ __launch_bounds__(256) void att2_kernel(
    const float* __restrict__ h, const float* __restrict__ W_dec,
    const float* __restrict__ b_dec, const float* __restrict__ b_enc,
    const float* __restrict__ W_beta, const float* __restrict__ b_beta) {
    int b = blockIdx.x, t = threadIdx.x;
    __shared__ float hs[DEC];
    __shared__ float red[256];
    hs[t] = h[b * DEC + t];
    hs[t + 256] = h[b * DEC + t + 256];
    __syncthreads();
    float acc0 = 0.f, acc1 = 0.f;
#pragma unroll 8
    for (int k = 0; k < DEC; k++) {
        float hv = hs[k];
        acc0 += hv * W_dec[k * ATTD + t];
        acc1 += hv * W_dec[k * ATTD + t + 256];
    }
    g_att2[b * ATTD + t] = acc0 + b_dec[t] + b_enc[t];
    g_att2[b * ATTD + t + 256] = acc1 + b_dec[t + 256] + b_enc[t + 256];
    float p = hs[t] * W_beta[t] + hs[t + 256] * W_beta[t + 256];
    red[t] = p;
    __syncthreads();
    for (int s = 128; s > 0; s >>= 1) {
        if (t < s) red[t] += red[t + s];
        __syncthreads();
    }
    if (t == 0) g_gate[b] = 1.f / (1.f + expf(-(red[0] + b_beta[0])));
}

// ---------------------------------------------------------------------------
// Main GEMM: 256 threads, 2 CTAs/SM. 8 warps = 4m x 2n, warp m32 x n64.
// 4 n-chunks of 128. nb==0: x LDG+cvt (+.cs side-write to g_Xh);
// nb>=1: x cp.async straight from g_Xh (no cvt, no regs).
// ---------------------------------------------------------------------------
__global__ __launch_bounds__(NTH, 2) void att_gemm_mma(
    const float* __restrict__ x, const float* __restrict__ W_full) {
    extern __shared__ unsigned char dynraw[];
    __shared__ float wf_s[ATTD];
    __shared__ float att_acc[TILE_M];

    const int tid = threadIdx.x;
    const int lane = tid & 31;
    const int wid = tid >> 5;
    const int wm = wid >> 1;   // 0..3
    const int wn = wid & 1;    // 0..1
    const int row0 = blockIdx.x * TILE_M;

    uint32_t rawb = smem_u32(dynraw);
    uint32_t dynb = (rawb + 127u) & ~127u;
    unsigned char* dyn = dynraw + (dynb - rawb);

    wf_s[tid] = W_full[tid];
    wf_s[tid + 256] = W_full[tid + 256];
    if (tid < TILE_M) att_acc[tid] = 0.f;
    __syncthreads();

    // nb==0 x converter mapping: 2 threads/row, 32 elems each
    const int xm = tid >> 1, xh = tid & 1;
    const int xs7 = xm & 7;
    const float4* xg = reinterpret_cast<const float4*>(x) +
                       (size_t)(row0 + xm) * (ENC / 4) + xh * 8;
    __half* xh_base = g_Xh + (size_t)(row0 + xm) * ENC + xh * 32;

    // ldmatrix lane geometry (4m x 2n; warp m32 x n64)
    const int a_r = wm * 32 + (lane & 15);
    const int a_hi = lane >> 4;
    const int b_r = wn * 64 + (lane & 7) + ((lane >> 1) & 8);
    const int b_hi = (lane >> 3) & 1;

    for (int nb = 0; nb < NB_CHUNKS; nb++) {
        float acc[2][8][4];
#pragma unroll
        for (int mt = 0; mt < 2; mt++)
#pragma unroll
            for (int nt = 0; nt < 8; nt++)
#pragma unroll
                for (int q = 0; q < 4; q++) acc[mt][nt][q] = 0.f;

        // ---- prologue ----
        if (nb == 0) {
            // x stage 0: LDG + cvt + STS + side-write
            {
                float4 v[8];
#pragma unroll
                for (int j = 0; j < 8; j++) v[j] = xg[j];
                const float* e = reinterpret_cast<const float*>(v);
                uint32_t hw[16];
#pragma unroll
                for (int q = 0; q < 16; q++)
                    hw[q] = packh2(__float2half_rn(e[2 * q]), __float2half_rn(e[2 * q + 1]));
#pragma unroll
                for (int jj = 0; jj < 4; jj++) {
                    int c = xh * 4 + jj;
                    *reinterpret_cast<uint4*>(dyn + xm * 128 + ((c ^ xs7) << 4)) =
                        make_uint4(hw[4 * jj], hw[4 * jj + 1], hw[4 * jj + 2], hw[4 * jj + 3]);
                    stg_cs_128(xh_base + jj * 8,
                               make_uint4(hw[4 * jj], hw[4 * jj + 1], hw[4 * jj + 2], hw[4 * jj + 3]));
                }
            }
            // W stages 0,1
#pragma unroll
            for (int p = 0; p < 2; p++) {
#pragma unroll
                for (int j = 0; j < 4; j++) {
                    int i = tid + NTH * j;
                    int row = i >> 3, c = i & 7;
                    uint32_t dst = dynb + WBASE + p * WSTG + row * 128 +
                                   ((c ^ (row & 7)) << 4);
                    const unsigned char* src = g_Wt +
                        (size_t)(nb * 128 + row) * 4096 + (size_t)(p * KBLK + c * 8) * 2;
                    CP_ASYNC16(dst, src);
                }
                CP_COMMIT();
            }
        } else {
            // x + W stages 0,1 both via cp.async
#pragma unroll
            for (int p = 0; p < 2; p++) {
#pragma unroll
                for (int j = 0; j < 4; j++) {
                    int i = tid + NTH * j;
                    int row = i >> 3, c = i & 7;
                    uint32_t sw = ((c ^ (row & 7)) << 4);
                    CP_ASYNC16(dynb + p * XSTG + row * 128 + sw,
                               reinterpret_cast<const unsigned char*>(
                                   g_Xh + (size_t)(row0 + row) * ENC + p * KBLK + c * 8));
                    CP_ASYNC16(dynb + WBASE + p * WSTG + row * 128 + sw,
                               g_Wt + (size_t)(nb * 128 + row) * 4096 +
                                   (size_t)(p * KBLK + c * 8) * 2);
                }
                CP_COMMIT();
            }
        }

        for (int kblk = 0; kblk < NKB; kblk++) {
            const int st = kblk % NSTG;
            const bool more = (kblk + 1 < NKB);
            float4 xr[8];
            if (nb == 0 && more) {
                const float4* p = xg + (kblk + 1) * 16;
#pragma unroll
                for (int j = 0; j < 8; j++) xr[j] = p[j];
            }
            CP_WAIT1();
            __syncthreads();

            // nb==0: cvt + STS x(kblk+1) BEFORE MMA (kills register liveness)
            if (nb == 0 && more) {
                const int xs = (kblk + 1) % NSTG;
                const float* e = reinterpret_cast<const float*>(xr);
                uint32_t hw[16];
#pragma unroll
                for (int q = 0; q < 16; q++)
                    hw[q] = packh2(__float2half_rn(e[2 * q]), __float2half_rn(e[2 * q + 1]));
                unsigned char* xb = dyn + xs * XSTG;
                __half* xo = xh_base + (size_t)(kblk + 1) * KBLK;
#pragma unroll
                for (int jj = 0; jj < 4; jj++) {
                    int c = xh * 4 + jj;
                    *reinterpret_cast<uint4*>(xb + xm * 128 + ((c ^ xs7) << 4)) =
                        make_uint4(hw[4 * jj], hw[4 * jj + 1], hw[4 * jj + 2], hw[4 * jj + 3]);
                    stg_cs_128(xo + jj * 8,
                               make_uint4(hw[4 * jj], hw[4 * jj + 1], hw[4 * jj + 2], hw[4 * jj + 3]));
                }
            }

            // issue stage kblk+2 (x for nb>=1, W always); empty commit otherwise
            if (kblk + 2 < NKB) {
                const int ws = (kblk + 2) % NSTG;
#pragma unroll
                for (int j = 0; j < 4; j++) {
                    int i = tid + NTH * j;
                    int row = i >> 3, c = i & 7;
                    uint32_t sw = ((c ^ (row & 7)) << 4);
                    if (nb != 0) {
                        CP_ASYNC16(dynb + ws * XSTG + row * 128 + sw,
                                   reinterpret_cast<const unsigned char*>(
                                       g_Xh + (size_t)(row0 + row) * ENC +
                                       (size_t)(kblk + 2) * KBLK + c * 8));
                    }
                    CP_ASYNC16(dynb + WBASE + ws * WSTG + row * 128 + sw,
                               g_Wt + (size_t)(nb * 128 + row) * 4096 +
                                   (size_t)((kblk + 2) * KBLK + c * 8) * 2);
                }
            }
            CP_COMMIT();

            // ---- MMA on stage st ----
            {
                const uint32_t xsb = dynb + st * XSTG;
                const uint32_t wsb = dynb + WBASE + st * WSTG;
#pragma unroll
                for (int ks = 0; ks < 4; ks++) {
                    uint32_t ah[2][4];
#pragma unroll
                    for (int mt = 0; mt < 2; mt++) {
                        int row = a_r + mt * 16;
                        uint32_t ad = xsb + row * 128 +
                                      (((ks * 2 + a_hi) ^ (row & 7)) << 4);
                        LDSM_X4(ah[mt], ad);
                    }
#pragma unroll
                    for (int ntp = 0; ntp < 4; ntp++) {
                        int row = b_r + ntp * 16;
                        uint32_t bd = wsb + row * 128 +
                                      (((ks * 2 + b_hi) ^ (row & 7)) << 4);
                        uint32_t bh[4];
                        LDSM_X4(bh, bd);
#pragma unroll
                        for (int mt = 0; mt < 2; mt++) {
                            MMA_F16F32(acc[mt][2 * ntp],     ah[mt], bh + 0);
                            MMA_F16F32(acc[mt][2 * ntp + 1], ah[mt], bh + 2);
                        }
                    }
                }
            }
        }
        CP_WAIT0();
        __syncthreads();

        // ---- epilogue for this n-chunk ----
#pragma unroll
        for (int mt = 0; mt < 2; mt++)
#pragma unroll
            for (int rh = 0; rh < 2; rh++) {
                int ml = wm * 32 + mt * 16 + (lane >> 2) + rh * 8;
                int gm = row0 + ml;
                int b = gm / LSEQ;
                const float* a2 = g_att2 + (size_t)b * ATTD + nb * 128 + wn * 64;
                const float* wfp = wf_s + nb * 128 + wn * 64;
                float s = 0.f;
#pragma unroll
                for (int nt = 0; nt < 8; nt++) {
#pragma unroll
                    for (int e2 = 0; e2 < 2; e2++) {
                        int nn = nt * 8 + (lane & 3) * 2 + e2;
                        float v = acc[mt][nt][rh * 2 + e2] + __ldg(a2 + nn);
                        s += fmaxf(v, 0.f) * wfp[nn];
                    }
                }
                s += __shfl_xor_sync(0xFFFFFFFF, s, 1);
                s += __shfl_xor_sync(0xFFFFFFFF, s, 2);
                if ((lane & 3) == 0) atomicAdd(&att_acc[ml], s);
            }
        __syncthreads();
    }

    if (tid < TILE_M) g_att[row0 + tid] = att_acc[tid];
}

// ---------------------------------------------------------------------------
// softmax over L
// ---------------------------------------------------------------------------
__global__ __launch_bounds__(256) void softmax_kernel(float* __restrict__ out_alpha) {
    int b = blockIdx.x, t = threadIdx.x;
    __shared__ float sred[256];
    float v = (t < LSEQ) ? g_att[b * LSEQ + t] : -1e30f;
    sred[t] = v;
    __syncthreads();
    for (int s = 128; s > 0; s >>= 1) {
        if (t < s) sred[t] = fmaxf(sred[t], sred[t + s]);
        __syncthreads();
    }
    float m = sred[0];
    __syncthreads();
    float e = (t < LSEQ) ? expf(v - m) : 0.f;
    sred[t] = e;
    __syncthreads();
    for (int s = 128; s > 0; s >>= 1) {
        if (t < s) sred[t] += sred[t + s];
        __syncthreads();
    }
    float inv = 1.f / sred[0];
    if (t < LSEQ) out_alpha[b * LSEQ + t] = e * inv;
}

// ---------------------------------------------------------------------------
// z from fp16 x copy: grid (BATCH, 2), 128 threads
// ---------------------------------------------------------------------------
__global__ __launch_bounds__(128) void z_kernel(
    const float* __restrict__ alpha, float* __restrict__ out_z) {
    int b = blockIdx.x;
    int half = blockIdx.y;
    int t = threadIdx.x;
    int col = half * 128 + t;
    __shared__ float sal[LSEQ];
    for (int i = t; i < LSEQ; i += 128) sal[i] = alpha[b * LSEQ + i];
    __syncthreads();
    const uint4* xp = reinterpret_cast<const uint4*>(g_Xh + (size_t)b * LSEQ * ENC) + col;
    float a0[8] = {0, 0, 0, 0, 0, 0, 0, 0};
#pragma unroll 4
    for (int l = 0; l < LSEQ; l++) {
        float a = sal[l];
        uint4 v = __ldg(xp + (size_t)l * (ENC / 8));
        const __half2* hh = reinterpret_cast<const __half2*>(&v);
#pragma unroll
        for (int j = 0; j < 4; j++) {
            float2 f = __half22float2(hh[j]);
            a0[2 * j] += a * f.x;
            a0[2 * j + 1] += a * f.y;
        }
    }
    float g = g_gate[b];
    float4 oa = {g * a0[0], g * a0[1], g * a0[2], g * a0[3]};
    float4 ob = {g * a0[4], g * a0[5], g * a0[6], g * a0[7]};
    float4* zp = reinterpret_cast<float4*>(out_z + (size_t)b * ENC);
    zp[2 * col] = oa;
    zp[2 * col + 1] = ob;
}

// ---------------------------------------------------------------------------
extern "C" void kernel_launch(void* const* d_in, const int* in_sizes, int n_in,
                              void* d_out, int out_size) {
    const float* x      = (const float*)d_in[0];
    const float* h      = (const float*)d_in[1];
    const float* W_enc  = (const float*)d_in[2];
    const float* b_enc  = (const float*)d_in[3];
    const float* W_dec  = (const float*)d_in[4];
    const float* b_dec  = (const float*)d_in[5];
    const float* W_full = (const float*)d_in[6];
    // d_in[7] = b_full: softmax-invariant, unused.
    const float* W_beta = (const float*)d_in[8];
    const float* b_beta = (const float*)d_in[9];

    float* out = (float*)d_out;
    float* out_z = out;
    float* out_alpha = out + (size_t)BATCH * ENC;

    cudaFuncSetAttribute(att_gemm_mma, cudaFuncAttributeMaxDynamicSharedMemorySize, DYN_BYTES);

    prep_w<<<dim3(ENC / 64, ATTD / 64), 256>>>(W_enc);
    att2_kernel<<<BATCH, 256>>>(h, W_dec, b_dec, b_enc, W_beta, b_beta);
    att_gemm_mma<<<NCTA, NTH, DYN_BYTES>>>(x, W_full);
    softmax_kernel<<<BATCH, 256>>>(out_alpha);
    z_kernel<<<dim3(BATCH, 2), 128>>>(out_alpha, out_z);
}